// round 12
// baseline (speedup 1.0000x reference)
#include <cuda_runtime.h>
#include <cuda_bf16.h>

#define B_TOTAL        65536
#define N_K            64
#define ROW_FLOATS     (N_K * 3)          // 192 floats per row per tensor
#define DEGREE         3
#define SAMPLES        20
#define ROWS_PER_BLOCK 16
#define THREADS        160                 // each thread: sample j of rows r and r+8
#define NBLOCKS        (B_TOTAL / ROWS_PER_BLOCK)  // 4096
#define KF_LEN         68                 // 4 zeros + 64 knots (fp32)
#define C_LEN          68                 // 64 bf16x2 coeff words + 4 pad

__device__ double        g_sum;     // zero-init; reset by last block each run
__device__ unsigned int  g_count;   // zero-init; reset by last block each run

// De Boor sample. kf padded fp32; coeffs packed bf16x2 (x=lo, y=hi).
__device__ __forceinline__ void deboor_eval(const float*    __restrict__ kf,
                                            const unsigned* __restrict__ c,
                                            float t, int i0,
                                            float& ox, float& oy)
{
    float kfv[7];
#pragma unroll
    for (int m = 1; m < 7; m++) kfv[m] = kf[i0 + m];   // kfv[0] never used

    float px[4], py[4];
#pragma unroll
    for (int k = 0; k < 4; k++) {
        unsigned w = c[i0 + k];
        float2 v = __bfloat1622float2(*reinterpret_cast<__nv_bfloat162*>(&w));
        px[k] = v.x; py[k] = v.y;
    }

#pragma unroll
    for (int l = 1; l <= DEGREE; l++) {
#pragma unroll
        for (int k = 3; k >= 1; k--) {
            if (k < l) break;
            float ki = kfv[k];
            float kj = kfv[k + 4 - l];
            float denom = kj - ki;
            float alpha = (denom != 0.0f) ? __fdividef(t - ki, denom) : 0.0f;
            px[k] = fmaf(alpha, px[k] - px[k - 1], px[k - 1]);
            py[k] = fmaf(alpha, py[k] - py[k - 1], py[k - 1]);
        }
    }
    ox = px[3];   // homogeneous weight stays exactly 1 -> no division
    oy = py[3];
}

__global__ __launch_bounds__(THREADS)
void bspline_loss_fused(const float* __restrict__ pred,
                        const float* __restrict__ tru,
                        float* __restrict__ out)
{
    __shared__ float         s_kf[2][ROWS_PER_BLOCK][KF_LEN];
    __shared__ unsigned      s_c [2][ROWS_PER_BLOCK][C_LEN];
    __shared__ unsigned char s_i0[2][ROWS_PER_BLOCK][SAMPLES];  // interval index per sample

    // Zero kf padding with STS.128: 32 (tensor,row) pairs.
    if (threadIdx.x < 2 * ROWS_PER_BLOCK) {
        int tsel = threadIdx.x >> 4;
        int r    = threadIdx.x & 15;
        *reinterpret_cast<float4*>(&s_kf[tsel][r][0]) = make_float4(0.f, 0.f, 0.f, 0.f);
    }

    // Wide transpose + direct i0 scatter.
    // 1 item = 4 triples: 3 LDG.128, 1 fp32 STS.128 (knots), 1 bf16x2 STS.128
    // (coeffs), plus interval-ownership scatter into s_i0 (uniform sample grid:
    // knot i owns samples j in [ceil(19*k_i/h), ceil(19*k_{i+1}/h)) with i0=i+1).
    {
        const size_t base = (size_t)blockIdx.x * ROWS_PER_BLOCK * ROW_FLOATS;
        const float4* gp = reinterpret_cast<const float4*>(pred + base);
        const float4* gt = reinterpret_cast<const float4*>(tru + base);
        const float*  fp = pred + base;
        const float*  ft = tru  + base;
        const int G = 2 * ROWS_PER_BLOCK * 16;
        for (int g = threadIdx.x; g < G; g += THREADS) {
            const int tsel = g >> 8;           // 0..1
            const int r    = (g >> 4) & 15;    // 0..15
            const int grp  = g & 15;           // 0..15 -> elements 4*grp..4*grp+3
            const float4* src  = tsel ? gt : gp;
            const float*  srcf = tsel ? ft : fp;
            const int idx4 = 48 * r + 3 * grp;
            float4 v0 = src[idx4 + 0];   // k0 x0 y0 k1
            float4 v1 = src[idx4 + 1];   // x1 y1 k2 x2
            float4 v2 = src[idx4 + 2];   // y2 k3 x3 y3
            const int i = 4 * grp;
            *reinterpret_cast<float4*>(&s_kf[tsel][r][4 + i]) =
                make_float4(v0.x, v0.w, v1.z, v2.y);

            __nv_bfloat162 c0 = __float22bfloat162_rn(make_float2(v0.y, v0.z));
            __nv_bfloat162 c1 = __float22bfloat162_rn(make_float2(v1.x, v1.y));
            __nv_bfloat162 c2 = __float22bfloat162_rn(make_float2(v1.w, v2.x));
            __nv_bfloat162 c3 = __float22bfloat162_rn(make_float2(v2.z, v2.w));
            uint4 packed;
            packed.x = *reinterpret_cast<unsigned*>(&c0);
            packed.y = *reinterpret_cast<unsigned*>(&c1);
            packed.z = *reinterpret_cast<unsigned*>(&c2);
            packed.w = *reinterpret_cast<unsigned*>(&c3);
            *reinterpret_cast<uint4*>(&s_c[tsel][r][i]) = packed;

            // i0 scatter (knots with global index < 60 only -> grp < 15).
            if (grp < 15) {
                const float h = __ldg(srcf + r * ROW_FLOATS + 180);   // knots[60]
                const float inv19h = __fdividef(19.0f, h);
                float kn[5];
                kn[0] = v0.x; kn[1] = v0.w; kn[2] = v1.z; kn[3] = v2.y;
                // next group's first knot (index 4*grp+4); for grp==14 the
                // interval of knot 59 extends to sample 19 regardless.
                kn[4] = (grp < 15) ? __ldg(srcf + r * ROW_FLOATS + 12 * grp + 12) : 0.0f;
                int b[5];
#pragma unroll
                for (int q = 0; q < 5; q++) {
                    int bb = (int)ceilf(kn[q] * inv19h);
                    b[q] = bb < 0 ? 0 : bb;
                }
                if (grp == 14) b[4] = SAMPLES;   // knot 59 owns up to j=19
                // grp 0 additionally owns [0, b0) with i0 = 0.
                if (grp == 0) {
                    int hi0 = b[0] < SAMPLES ? b[0] : SAMPLES;
                    for (int j = 0; j < hi0; j++) s_i0[tsel][r][j] = 0;
                }
#pragma unroll
                for (int q = 0; q < 4; q++) {
                    int lo = b[q];
                    int hi = b[q + 1] < SAMPLES ? b[q + 1] : SAMPLES;
                    unsigned char v = (unsigned char)(i + q + 1);
                    for (int j = lo; j < hi; j++) s_i0[tsel][r][j] = v;
                }
            }
        }
    }
    __syncthreads();

    // Thread -> (rows rA, rB = rA+8; sample j). 4 independent work chains,
    // no search: i0 comes from the precomputed table (broadcast byte loads).
    const int rA = threadIdx.x / SAMPLES;          // 0..7
    const int rB = rA + 8;                         // 8..15
    const int j  = threadIdx.x % SAMPLES;
    const float frac = (float)j / 19.0f;

    const float* kAp = &s_kf[0][rA][0];
    const float* kAt = &s_kf[1][rA][0];
    const float* kBp = &s_kf[0][rB][0];
    const float* kBt = &s_kf[1][rB][0];

    const float tAp = frac * kAp[64];
    const float tAt = frac * kAt[64];
    const float tBp = frac * kBp[64];
    const float tBt = frac * kBt[64];

    const int iAp = s_i0[0][rA][j];
    const int iAt = s_i0[1][rA][j];
    const int iBp = s_i0[0][rB][j];
    const int iBt = s_i0[1][rB][j];

    float pxA, pyA, txA, tyA;
    deboor_eval(kAp, &s_c[0][rA][0], tAp, iAp, pxA, pyA);
    deboor_eval(kAt, &s_c[1][rA][0], tAt, iAt, txA, tyA);
    float pxB, pyB, txB, tyB;
    deboor_eval(kBp, &s_c[0][rB][0], tBp, iBp, pxB, pyB);
    deboor_eval(kBt, &s_c[1][rB][0], tBt, iBt, txB, tyB);

    float dxA = pxA - txA, dyA = pyA - tyA;
    float dxB = pxB - txB, dyB = pyB - tyB;
    float val = fmaf(dxA, dxA, dyA * dyA) + fmaf(dxB, dxB, dyB * dyB);

    // Warp reduce (5 full warps).
#pragma unroll
    for (int o = 16; o > 0; o >>= 1)
        val += __shfl_down_sync(0xFFFFFFFFu, val, o);

    __shared__ float warpsum[THREADS / 32];
    const int wid  = threadIdx.x >> 5;
    const int lane = threadIdx.x & 31;
    if (lane == 0) warpsum[wid] = val;
    __syncthreads();

    if (threadIdx.x == 0) {
        double tot = 0.0;
#pragma unroll
        for (int w = 0; w < THREADS / 32; w++) tot += (double)warpsum[w];
        atomicAdd(&g_sum, tot);
        __threadfence();
        unsigned int ticket = atomicAdd(&g_count, 1u);
        if (ticket == NBLOCKS - 1) {
            out[0] = (float)(g_sum / (double)((long long)B_TOTAL * SAMPLES));
            g_sum = 0.0;
            __threadfence();
            g_count = 0u;
        }
    }
}

extern "C" void kernel_launch(void* const* d_in, const int* in_sizes, int n_in,
                              void* d_out, int out_size)
{
    const float* pred = (const float*)d_in[0];
    const float* tru  = (const float*)d_in[1];
    float* out = (float*)d_out;

    bspline_loss_fused<<<NBLOCKS, THREADS>>>(pred, tru, out);
}

// round 13
// speedup vs baseline: 1.3391x; 1.3391x over previous
#include <cuda_runtime.h>
#include <cuda_bf16.h>

#define B_TOTAL        65536
#define N_K            64
#define ROW_FLOATS     (N_K * 3)          // 192 floats per row per tensor
#define DEGREE         3
#define SAMPLES        20
#define ROWS_PER_BLOCK 32
#define THREADS        320                 // each thread: sample j of rows r and r+16
#define NBLOCKS        (B_TOTAL / ROWS_PER_BLOCK)  // 2048
#define KF_LEN         68                 // 4 zeros + 64 knots (fp32, exact search)
#define C_LEN          68                 // 64 bf16x2 coeff words + 4 pad

__device__ double        g_sum;     // zero-init; reset by last block each run
__device__ unsigned int  g_count;   // zero-init; reset by last block each run

// De Boor sample. kf padded fp32; coeffs packed bf16x2 (x=lo, y=hi).
__device__ __forceinline__ void deboor_eval(const float*    __restrict__ kf,
                                            const unsigned* __restrict__ c,
                                            float t, int i0,
                                            float& ox, float& oy)
{
    float kfv[7];
#pragma unroll
    for (int m = 1; m < 7; m++) kfv[m] = kf[i0 + m];   // kfv[0] never used

    float px[4], py[4];
#pragma unroll
    for (int k = 0; k < 4; k++) {
        unsigned w = c[i0 + k];
        float2 v = __bfloat1622float2(*reinterpret_cast<__nv_bfloat162*>(&w));
        px[k] = v.x; py[k] = v.y;
    }

#pragma unroll
    for (int l = 1; l <= DEGREE; l++) {
#pragma unroll
        for (int k = 3; k >= 1; k--) {
            if (k < l) break;
            float ki = kfv[k];
            float kj = kfv[k + 4 - l];
            float denom = kj - ki;
            float alpha = (denom != 0.0f) ? __fdividef(t - ki, denom) : 0.0f;
            px[k] = fmaf(alpha, px[k] - px[k - 1], px[k - 1]);
            py[k] = fmaf(alpha, py[k] - py[k - 1], py[k - 1]);
        }
    }
    ox = px[3];   // homogeneous weight stays exactly 1 -> no division
    oy = py[3];
}

// Quad-interleaved branchless searches: 4 independent LDS per round (MLP=4).
// Bounds: after steps 32,16,8,4 the index can be at most 60, so only the
// step=2 and step=1 rounds need the <=60 guard.
__device__ __forceinline__ void quad_knot_search(const float* __restrict__ k0, float t0,
                                                 const float* __restrict__ k1, float t1,
                                                 const float* __restrict__ k2, float t2,
                                                 const float* __restrict__ k3, float t3,
                                                 int& r0, int& r1, int& r2, int& r3)
{
    int a0 = 0, a1 = 0, a2 = 0, a3 = 0;
#pragma unroll
    for (int step = 32; step >= 4; step >>= 1) {
        int c0 = a0 + step, c1 = a1 + step, c2 = a2 + step, c3 = a3 + step;
        if (k0[c0 + 3] <= t0) a0 = c0;
        if (k1[c1 + 3] <= t1) a1 = c1;
        if (k2[c2 + 3] <= t2) a2 = c2;
        if (k3[c3 + 3] <= t3) a3 = c3;
    }
#pragma unroll
    for (int step = 2; step >= 1; step >>= 1) {
        int c0 = a0 + step, c1 = a1 + step, c2 = a2 + step, c3 = a3 + step;
        if (c0 <= 60 && k0[c0 + 3] <= t0) a0 = c0;
        if (c1 <= 60 && k1[c1 + 3] <= t1) a1 = c1;
        if (c2 <= 60 && k2[c2 + 3] <= t2) a2 = c2;
        if (c3 <= 60 && k3[c3 + 3] <= t3) a3 = c3;
    }
    r0 = a0; r1 = a1; r2 = a2; r3 = a3;
}

__global__ __launch_bounds__(THREADS)
void bspline_loss_fused(const float* __restrict__ pred,
                        const float* __restrict__ tru,
                        float* __restrict__ out)
{
    __shared__ float    s_kf[2][ROWS_PER_BLOCK][KF_LEN];
    __shared__ unsigned s_c [2][ROWS_PER_BLOCK][C_LEN];

    // Zero kf padding with STS.128: 64 (tensor,row) pairs.
    if (threadIdx.x < 2 * ROWS_PER_BLOCK) {
        int tsel = threadIdx.x >> 5;
        int r    = threadIdx.x & 31;
        *reinterpret_cast<float4*>(&s_kf[tsel][r][0]) = make_float4(0.f, 0.f, 0.f, 0.f);
    }

    // Wide transpose: 1 item = 4 triples = 3 LDG.128 in, 1 fp32 STS.128 (knots)
    // + 1 packed-bf16x2 STS.128 (4 coeff points) out.
    // items = 2 tensors x 32 rows x 16 groups = 1024.
    {
        const size_t base = (size_t)blockIdx.x * ROWS_PER_BLOCK * ROW_FLOATS;
        const float4* gp = reinterpret_cast<const float4*>(pred + base);
        const float4* gt = reinterpret_cast<const float4*>(tru + base);
        const int G = 2 * ROWS_PER_BLOCK * 16;
        for (int g = threadIdx.x; g < G; g += THREADS) {
            const int tsel = g >> 9;           // 0..1
            const int r    = (g >> 4) & 31;    // 0..31
            const int grp  = g & 15;           // 0..15 -> elements 4*grp..4*grp+3
            const float4* src = tsel ? gt : gp;
            const int idx4 = 48 * r + 3 * grp;
            float4 v0 = src[idx4 + 0];   // k0 x0 y0 k1
            float4 v1 = src[idx4 + 1];   // x1 y1 k2 x2
            float4 v2 = src[idx4 + 2];   // y2 k3 x3 y3
            const int i = 4 * grp;
            *reinterpret_cast<float4*>(&s_kf[tsel][r][4 + i]) =
                make_float4(v0.x, v0.w, v1.z, v2.y);

            __nv_bfloat162 c0 = __float22bfloat162_rn(make_float2(v0.y, v0.z));
            __nv_bfloat162 c1 = __float22bfloat162_rn(make_float2(v1.x, v1.y));
            __nv_bfloat162 c2 = __float22bfloat162_rn(make_float2(v1.w, v2.x));
            __nv_bfloat162 c3 = __float22bfloat162_rn(make_float2(v2.z, v2.w));
            uint4 packed;
            packed.x = *reinterpret_cast<unsigned*>(&c0);
            packed.y = *reinterpret_cast<unsigned*>(&c1);
            packed.z = *reinterpret_cast<unsigned*>(&c2);
            packed.w = *reinterpret_cast<unsigned*>(&c3);
            *reinterpret_cast<uint4*>(&s_c[tsel][r][i]) = packed;
        }
    }
    __syncthreads();

    // Thread -> (rows rA, rB = rA+16; sample j). 4 independent work chains.
    const int rA = threadIdx.x / SAMPLES;          // 0..15
    const int rB = rA + 16;                        // 16..31
    const int j  = threadIdx.x % SAMPLES;
    const float frac = (float)j / 19.0f;

    const float* kAp = &s_kf[0][rA][0];
    const float* kAt = &s_kf[1][rA][0];
    const float* kBp = &s_kf[0][rB][0];
    const float* kBt = &s_kf[1][rB][0];

    const float tAp = frac * kAp[64];
    const float tAt = frac * kAt[64];
    const float tBp = frac * kBp[64];
    const float tBt = frac * kBt[64];

    int iAp, iAt, iBp, iBt;
    quad_knot_search(kAp, tAp, kAt, tAt, kBp, tBp, kBt, tBt, iAp, iAt, iBp, iBt);

    float pxA, pyA, txA, tyA;
    deboor_eval(kAp, &s_c[0][rA][0], tAp, iAp, pxA, pyA);
    deboor_eval(kAt, &s_c[1][rA][0], tAt, iAt, txA, tyA);
    float pxB, pyB, txB, tyB;
    deboor_eval(kBp, &s_c[0][rB][0], tBp, iBp, pxB, pyB);
    deboor_eval(kBt, &s_c[1][rB][0], tBt, iBt, txB, tyB);

    float dxA = pxA - txA, dyA = pyA - tyA;
    float dxB = pxB - txB, dyB = pyB - tyB;
    float val = fmaf(dxA, dxA, dyA * dyA) + fmaf(dxB, dxB, dyB * dyB);

    // Warp reduce (10 full warps).
#pragma unroll
    for (int o = 16; o > 0; o >>= 1)
        val += __shfl_down_sync(0xFFFFFFFFu, val, o);

    __shared__ float warpsum[THREADS / 32];
    const int wid  = threadIdx.x >> 5;
    const int lane = threadIdx.x & 31;
    if (lane == 0) warpsum[wid] = val;
    __syncthreads();

    if (threadIdx.x == 0) {
        double tot = 0.0;
#pragma unroll
        for (int w = 0; w < THREADS / 32; w++) tot += (double)warpsum[w];
        atomicAdd(&g_sum, tot);
        __threadfence();
        unsigned int ticket = atomicAdd(&g_count, 1u);
        if (ticket == NBLOCKS - 1) {
            out[0] = (float)(g_sum / (double)((long long)B_TOTAL * SAMPLES));
            g_sum = 0.0;
            __threadfence();
            g_count = 0u;
        }
    }
}

extern "C" void kernel_launch(void* const* d_in, const int* in_sizes, int n_in,
                              void* d_out, int out_size)
{
    const float* pred = (const float*)d_in[0];
    const float* tru  = (const float*)d_in[1];
    float* out = (float*)d_out;

    bspline_loss_fused<<<NBLOCKS, THREADS>>>(pred, tru, out);
}

// round 14
// speedup vs baseline: 1.3643x; 1.0188x over previous
#include <cuda_runtime.h>
#include <cuda_bf16.h>
#include <cstdint>

#define B_TOTAL        65536
#define N_K            64
#define ROW_FLOATS     (N_K * 3)          // 192 floats per row per tensor
#define DEGREE         3
#define SAMPLES        20
#define ROWS_PER_BLOCK 16
#define THREADS        160                 // each thread: sample j of rows r and r+8
#define NBLOCKS        (B_TOTAL / ROWS_PER_BLOCK)  // 4096
#define KF_LEN         68                 // 4 zeros + 64 knots (fp32, exact search)
#define C_LEN          68                 // 64 bf16x2 coeff words + 4 pad

__device__ double        g_sum;     // zero-init; reset by last block each run
__device__ unsigned int  g_count;   // zero-init; reset by last block each run

// Packed f32x2 helpers (sm_103a native paired fp32 pipes).
__device__ __forceinline__ uint64_t pack2(float lo, float hi) {
    uint64_t r;
    asm("mov.b64 %0, {%1, %2};" : "=l"(r) : "f"(lo), "f"(hi));
    return r;
}
__device__ __forceinline__ void unpack2(uint64_t v, float& lo, float& hi) {
    asm("mov.b64 {%0, %1}, %2;" : "=f"(lo), "=f"(hi) : "l"(v));
}
__device__ __forceinline__ uint64_t sub_f32x2(uint64_t a, uint64_t b) {
    uint64_t r;
    asm("sub.rn.f32x2 %0, %1, %2;" : "=l"(r) : "l"(a), "l"(b));
    return r;
}
__device__ __forceinline__ uint64_t fma_f32x2(uint64_t a, uint64_t b, uint64_t c) {
    uint64_t r;
    asm("fma.rn.f32x2 %0, %1, %2, %3;" : "=l"(r) : "l"(a), "l"(b), "l"(c));
    return r;
}

// De Boor sample. kf padded fp32; coeffs packed bf16x2 (x=lo, y=hi).
// denom is provably > 0 (kj is a real knot with strictly larger index than ki;
// knots strictly increasing with spacing >= 0.1), so no zero guard is needed.
__device__ __forceinline__ uint64_t deboor_eval(const float*    __restrict__ kf,
                                                const unsigned* __restrict__ c,
                                                float t, int i0)
{
    float kfv[7];
#pragma unroll
    for (int m = 1; m < 7; m++) kfv[m] = kf[i0 + m];   // kfv[0] never used

    uint64_t p[4];                     // packed (x, y) control points
#pragma unroll
    for (int k = 0; k < 4; k++) {
        unsigned w = c[i0 + k];
        float2 v = __bfloat1622float2(*reinterpret_cast<__nv_bfloat162*>(&w));
        p[k] = pack2(v.x, v.y);
    }

#pragma unroll
    for (int l = 1; l <= DEGREE; l++) {
#pragma unroll
        for (int k = 3; k >= 1; k--) {
            if (k < l) break;
            float ki = kfv[k];
            float alpha = __fdividef(t - ki, kfv[k + 4 - l] - ki);
            uint64_t a2 = pack2(alpha, alpha);
            p[k] = fma_f32x2(a2, sub_f32x2(p[k], p[k - 1]), p[k - 1]);
        }
    }
    return p[3];   // homogeneous weight stays exactly 1 -> no division
}

// Quad-interleaved branchless searches: 4 independent LDS per round (MLP=4).
// Only the step=2 and step=1 rounds can exceed index 60, so only they carry
// the bound guard.
__device__ __forceinline__ void quad_knot_search(const float* __restrict__ k0, float t0,
                                                 const float* __restrict__ k1, float t1,
                                                 const float* __restrict__ k2, float t2,
                                                 const float* __restrict__ k3, float t3,
                                                 int& r0, int& r1, int& r2, int& r3)
{
    int a0 = 0, a1 = 0, a2 = 0, a3 = 0;
#pragma unroll
    for (int step = 32; step >= 4; step >>= 1) {
        int c0 = a0 + step, c1 = a1 + step, c2 = a2 + step, c3 = a3 + step;
        if (k0[c0 + 3] <= t0) a0 = c0;
        if (k1[c1 + 3] <= t1) a1 = c1;
        if (k2[c2 + 3] <= t2) a2 = c2;
        if (k3[c3 + 3] <= t3) a3 = c3;
    }
#pragma unroll
    for (int step = 2; step >= 1; step >>= 1) {
        int c0 = a0 + step, c1 = a1 + step, c2 = a2 + step, c3 = a3 + step;
        if (c0 <= 60 && k0[c0 + 3] <= t0) a0 = c0;
        if (c1 <= 60 && k1[c1 + 3] <= t1) a1 = c1;
        if (c2 <= 60 && k2[c2 + 3] <= t2) a2 = c2;
        if (c3 <= 60 && k3[c3 + 3] <= t3) a3 = c3;
    }
    r0 = a0; r1 = a1; r2 = a2; r3 = a3;
}

__global__ __launch_bounds__(THREADS)
void bspline_loss_fused(const float* __restrict__ pred,
                        const float* __restrict__ tru,
                        float* __restrict__ out)
{
    __shared__ float    s_kf[2][ROWS_PER_BLOCK][KF_LEN];
    __shared__ unsigned s_c [2][ROWS_PER_BLOCK][C_LEN];

    // Zero kf padding with STS.128: 32 (tensor,row) pairs.
    if (threadIdx.x < 2 * ROWS_PER_BLOCK) {
        int tsel = threadIdx.x >> 4;
        int r    = threadIdx.x & 15;
        *reinterpret_cast<float4*>(&s_kf[tsel][r][0]) = make_float4(0.f, 0.f, 0.f, 0.f);
    }

    // Wide transpose: 1 item = 4 triples = 3 LDG.128 in, 1 fp32 STS.128 (knots)
    // + 1 packed-bf16x2 STS.128 (4 coeff points) out.
    // items = 2 tensors x 16 rows x 16 groups = 512.
    {
        const size_t base = (size_t)blockIdx.x * ROWS_PER_BLOCK * ROW_FLOATS;
        const float4* gp = reinterpret_cast<const float4*>(pred + base);
        const float4* gt = reinterpret_cast<const float4*>(tru + base);
        const int G = 2 * ROWS_PER_BLOCK * 16;
        for (int g = threadIdx.x; g < G; g += THREADS) {
            const int tsel = g >> 8;           // 0..1
            const int r    = (g >> 4) & 15;    // 0..15
            const int grp  = g & 15;           // 0..15 -> elements 4*grp..4*grp+3
            const float4* src = tsel ? gt : gp;
            const int idx4 = 48 * r + 3 * grp;
            float4 v0 = src[idx4 + 0];   // k0 x0 y0 k1
            float4 v1 = src[idx4 + 1];   // x1 y1 k2 x2
            float4 v2 = src[idx4 + 2];   // y2 k3 x3 y3
            const int i = 4 * grp;
            *reinterpret_cast<float4*>(&s_kf[tsel][r][4 + i]) =
                make_float4(v0.x, v0.w, v1.z, v2.y);

            __nv_bfloat162 c0 = __float22bfloat162_rn(make_float2(v0.y, v0.z));
            __nv_bfloat162 c1 = __float22bfloat162_rn(make_float2(v1.x, v1.y));
            __nv_bfloat162 c2 = __float22bfloat162_rn(make_float2(v1.w, v2.x));
            __nv_bfloat162 c3 = __float22bfloat162_rn(make_float2(v2.z, v2.w));
            uint4 packed;
            packed.x = *reinterpret_cast<unsigned*>(&c0);
            packed.y = *reinterpret_cast<unsigned*>(&c1);
            packed.z = *reinterpret_cast<unsigned*>(&c2);
            packed.w = *reinterpret_cast<unsigned*>(&c3);
            *reinterpret_cast<uint4*>(&s_c[tsel][r][i]) = packed;
        }
    }
    __syncthreads();

    // Thread -> (rows rA, rB = rA+8; sample j). 4 independent work chains.
    const int rA = threadIdx.x / SAMPLES;          // 0..7
    const int rB = rA + 8;                         // 8..15
    const int j  = threadIdx.x % SAMPLES;
    const float frac = (float)j / 19.0f;

    const float* kAp = &s_kf[0][rA][0];
    const float* kAt = &s_kf[1][rA][0];
    const float* kBp = &s_kf[0][rB][0];
    const float* kBt = &s_kf[1][rB][0];

    const float tAp = frac * kAp[64];
    const float tAt = frac * kAt[64];
    const float tBp = frac * kBp[64];
    const float tBt = frac * kBt[64];

    int iAp, iAt, iBp, iBt;
    quad_knot_search(kAp, tAp, kAt, tAt, kBp, tBp, kBt, tBt, iAp, iAt, iBp, iBt);

    uint64_t sAp = deboor_eval(kAp, &s_c[0][rA][0], tAp, iAp);
    uint64_t sAt = deboor_eval(kAt, &s_c[1][rA][0], tAt, iAt);
    uint64_t sBp = deboor_eval(kBp, &s_c[0][rB][0], tBp, iBp);
    uint64_t sBt = deboor_eval(kBt, &s_c[1][rB][0], tBt, iBt);

    uint64_t dA = sub_f32x2(sAp, sAt);
    uint64_t dB = sub_f32x2(sBp, sBt);
    float dxA, dyA, dxB, dyB;
    unpack2(dA, dxA, dyA);
    unpack2(dB, dxB, dyB);
    float val = fmaf(dxA, dxA, dyA * dyA) + fmaf(dxB, dxB, dyB * dyB);

    // Warp reduce (5 full warps).
#pragma unroll
    for (int o = 16; o > 0; o >>= 1)
        val += __shfl_down_sync(0xFFFFFFFFu, val, o);

    __shared__ float warpsum[THREADS / 32];
    const int wid  = threadIdx.x >> 5;
    const int lane = threadIdx.x & 31;
    if (lane == 0) warpsum[wid] = val;
    __syncthreads();

    if (threadIdx.x == 0) {
        double tot = 0.0;
#pragma unroll
        for (int w = 0; w < THREADS / 32; w++) tot += (double)warpsum[w];
        atomicAdd(&g_sum, tot);
        __threadfence();
        unsigned int ticket = atomicAdd(&g_count, 1u);
        if (ticket == NBLOCKS - 1) {
            out[0] = (float)(g_sum / (double)((long long)B_TOTAL * SAMPLES));
            g_sum = 0.0;
            __threadfence();
            g_count = 0u;
        }
    }
}

extern "C" void kernel_launch(void* const* d_in, const int* in_sizes, int n_in,
                              void* d_out, int out_size)
{
    const float* pred = (const float*)d_in[0];
    const float* tru  = (const float*)d_in[1];
    float* out = (float*)d_out;

    bspline_loss_fused<<<NBLOCKS, THREADS>>>(pred, tru, out);
}